// round 14
// baseline (speedup 1.0000x reference)
#include <cuda_runtime.h>
#include <cstdint>

#define HID   16
#define BATCH 2048
#define SEQT  2048
#define FUT   32
#define NOUT  (FUT + 1)
#define WPB   4            // 4 warps/CTA, 128 CTAs -> 1 CTA/SM, ONE warp per SMSP
#define EPW   4            // elements per warp

typedef unsigned long long ull;

// ---------- packed f32x2 helpers (sm_103a) ----------
__device__ __forceinline__ ull pack2(float lo, float hi) {
    ull r;
    asm("mov.b64 %0, {%1, %2};" : "=l"(r) : "f"(lo), "f"(hi));
    return r;
}
__device__ __forceinline__ void unpack2(ull v, float& lo, float& hi) {
    asm("mov.b64 {%0, %1}, %2;" : "=f"(lo), "=f"(hi) : "l"(v));
}
__device__ __forceinline__ ull fma2(ull a, ull b, ull c) {
    ull d;
    asm("fma.rn.f32x2 %0, %1, %2, %3;" : "=l"(d) : "l"(a), "l"(b), "l"(c));
    return d;
}
__device__ __forceinline__ ull add2(ull a, ull b) {
    ull d;
    asm("add.rn.f32x2 %0, %1, %2;" : "=l"(d) : "l"(a), "l"(b));
    return d;
}
__device__ __forceinline__ float hadd2(ull v) {
    float lo, hi; unpack2(v, lo, hi); return lo + hi;
}

// ---------- fast activations ----------
__device__ __forceinline__ float tanh_ap(float x) {
    float y;
    asm("tanh.approx.f32 %0, %1;" : "=f"(y) : "f"(x));
    return y;
}
__device__ __forceinline__ float sigm(float x) {
    return fmaf(0.5f, tanh_ap(0.5f * x), 0.5f);
}

// ONE warp = FOUR batch elements; ONE warp per SMSP (no partner interference).
// lane = e*8 + u owns units 2u, 2u+1 of element e, all 4 gates each:
//   acc/row index q = 0..7 -> row R(q) = 2u + (q>>2) + 16*(q&3)
//   (q<4: gates i,f,g,o of unit 2u; q>=4: of unit 2u+1)
// Whh1 in registers (recurrence); Wih2/Whh2 in smem keyed by u (lane-broadcast).
// Steady-state step: [L2 gates(t) ; L1 gates(t+1)] -> 2x STS.64 -> ONE syncwarp
// -> merged matvec region (p2(t) + a2/p1(t+2): 192 fma2).
__global__ void __launch_bounds__(32 * WPB, 1)
lstm_net_kernel(const float* __restrict__ x,
                const float* __restrict__ Wih1, const float* __restrict__ Whh1,
                const float* __restrict__ bih1, const float* __restrict__ bhh1,
                const float* __restrict__ Wih2, const float* __restrict__ Whh2,
                const float* __restrict__ bih2, const float* __restrict__ bhh2,
                const float* __restrict__ fc1w, const float* __restrict__ fc1b,
                const float* __restrict__ fc2w, const float* __restrict__ fc2b,
                float* __restrict__ out)
{
    __shared__ ulonglong2 s_w2i[8][8][4];     // [kpair m][u][p] : Wih2 row pairs
    __shared__ ulonglong2 s_w2h[8][8][4];     // Whh2
    __shared__ ulonglong2 s_pb1[8][4];        // packed biases layer 1 [u][p]
    __shared__ ulonglong2 s_pb2[8][4];        // layer 2
    __shared__ ulonglong2 s_h1v[WPB][EPW][4]; // h1 broadcast (8 ull = k-pairs)
    __shared__ ulonglong2 s_h2v[WPB][EPW][4];
    __shared__ float s_fc1w[128];
    __shared__ float s_fc1b[8];
    __shared__ float s_fc2w[8];
    __shared__ float s_fc2b1[1];

    const int tid = threadIdx.x;
    for (int idx = tid; idx < 256; idx += 32 * WPB) {
        const int m = idx >> 5, uu = (idx >> 2) & 7, p = idx & 3;
        const int q0 = 2 * p, q1 = 2 * p + 1;
        const int r0 = 2 * uu + (q0 >> 2) + 16 * (q0 & 3);
        const int r1 = 2 * uu + (q1 >> 2) + 16 * (q1 & 3);
        s_w2i[m][uu][p] = make_ulonglong2(
            pack2(Wih2[r0 * HID + 2 * m], Wih2[r0 * HID + 2 * m + 1]),
            pack2(Wih2[r1 * HID + 2 * m], Wih2[r1 * HID + 2 * m + 1]));
        s_w2h[m][uu][p] = make_ulonglong2(
            pack2(Whh2[r0 * HID + 2 * m], Whh2[r0 * HID + 2 * m + 1]),
            pack2(Whh2[r1 * HID + 2 * m], Whh2[r1 * HID + 2 * m + 1]));
    }
    if (tid < 32) {
        const int uu = tid >> 2, p = tid & 3;
        const int q0 = 2 * p, q1 = 2 * p + 1;
        const int r0 = 2 * uu + (q0 >> 2) + 16 * (q0 & 3);
        const int r1 = 2 * uu + (q1 >> 2) + 16 * (q1 & 3);
        s_pb1[uu][p] = make_ulonglong2(pack2(bih1[r0] + bhh1[r0], 0.f),
                                       pack2(bih1[r1] + bhh1[r1], 0.f));
        s_pb2[uu][p] = make_ulonglong2(pack2(bih2[r0] + bhh2[r0], 0.f),
                                       pack2(bih2[r1] + bhh2[r1], 0.f));
    }
    if (tid < 128) s_fc1w[tid] = fc1w[tid];
    if (tid < 8) { s_fc1b[tid] = fc1b[tid]; s_fc2w[tid] = fc2w[tid]; }
    if (tid == 0) s_fc2b1[0] = fc2b[0];
    __syncthreads();

    const int lane = tid & 31;
    const int w    = tid >> 5;
    const int e    = lane >> 3;               // element within warp (0..3)
    const int u    = lane & 7;                // unit-pair index (units 2u, 2u+1)
    const int b    = (blockIdx.x * WPB + w) * EPW + e;

    // per-lane input weights (8 rows) + Whh1 k-pair packed: 8x8 ull = 128 regs
    float wx[8];
    ull w1[8][8];
#pragma unroll
    for (int q = 0; q < 8; ++q) {
        const int r = 2 * u + (q >> 2) + 16 * (q & 3);
        wx[q] = Wih1[r];
#pragma unroll
        for (int m = 0; m < 8; ++m)
            w1[q][m] = pack2(Whh1[r * HID + 2 * m], Whh1[r * HID + 2 * m + 1]);
    }

    const ull zero2 = pack2(0.f, 0.f);
    float c1a = 0.f, c1b = 0.f, c2a = 0.f, c2b = 0.f, o_head = 0.f;
    ull p1[8], s2[8];

    ull* myh1 = (ull*)&s_h1v[w][e][0];
    ull* myh2 = (ull*)&s_h2v[w][e][0];

    // init: zero h2 (prologue p2 = 0), p1 = packed layer-1 bias
    myh2[u] = zero2;
    {
        const ulonglong2 b0 = s_pb1[u][0], b1_ = s_pb1[u][1];
        const ulonglong2 b2_ = s_pb1[u][2], b3_ = s_pb1[u][3];
        p1[0] = b0.x;  p1[1] = b0.y;  p1[2] = b1_.x; p1[3] = b1_.y;
        p1[4] = b2_.x; p1[5] = b2_.y; p1[6] = b3_.x; p1[7] = b3_.y;
    }

    const float* xrow = x + (size_t)b * SEQT;
    float* orow = out + (size_t)b * NOUT;

    // ---- step segments ----
    auto l1gates = [&](float inp) {
        float uq[8];
#pragma unroll
        for (int q = 0; q < 8; ++q) uq[q] = fmaf(wx[q], inp, hadd2(p1[q]));
        const float ia = sigm(uq[0]), fa = sigm(uq[1]);
        const float ga = tanh_ap(uq[2]), oa = sigm(uq[3]);
        c1a = fmaf(fa, c1a, ia * ga);
        const float h1a = oa * tanh_ap(c1a);
        const float ib = sigm(uq[4]), fb = sigm(uq[5]);
        const float gb = tanh_ap(uq[6]), ob = sigm(uq[7]);
        c1b = fmaf(fb, c1b, ib * gb);
        const float h1b = ob * tanh_ap(c1b);
        myh1[u] = pack2(h1a, h1b);
    };

    auto l2gates = [&]() {
        float vq[8];
#pragma unroll
        for (int q = 0; q < 8; ++q) vq[q] = hadd2(s2[q]);
        const float ia = sigm(vq[0]), fa = sigm(vq[1]);
        const float ga = tanh_ap(vq[2]), oa = sigm(vq[3]);
        c2a = fmaf(fa, c2a, ia * ga);
        const float h2a = oa * tanh_ap(c2a);
        const float ib = sigm(vq[4]), fb = sigm(vq[5]);
        const float gb = tanh_ap(vq[6]), ob = sigm(vq[7]);
        c2b = fmaf(fb, c2b, ib * gb);
        const float h2b = ob * tanh_ap(c2b);
        myh2[u] = pack2(h2a, h2b);
    };

    // merged matvecs: p2 = Whh2@h2 ; a2 = b2 + Wih2@h1 ; p1 = b1 + Whh1@h1 ;
    // s2 = a2 + p2  (192 fma2, ~88 LDS, one syncwarp)
    auto matvecs = [&]() {
        __syncwarp();
        ull a2[8], p2[8];
        {
            const ulonglong2 b0 = s_pb2[u][0], b1_ = s_pb2[u][1];
            const ulonglong2 b2_ = s_pb2[u][2], b3_ = s_pb2[u][3];
            a2[0] = b0.x;  a2[1] = b0.y;  a2[2] = b1_.x; a2[3] = b1_.y;
            a2[4] = b2_.x; a2[5] = b2_.y; a2[6] = b3_.x; a2[7] = b3_.y;
        }
        {
            const ulonglong2 b0 = s_pb1[u][0], b1_ = s_pb1[u][1];
            const ulonglong2 b2_ = s_pb1[u][2], b3_ = s_pb1[u][3];
            p1[0] = b0.x;  p1[1] = b0.y;  p1[2] = b1_.x; p1[3] = b1_.y;
            p1[4] = b2_.x; p1[5] = b2_.y; p1[6] = b3_.x; p1[7] = b3_.y;
        }
#pragma unroll
        for (int q = 0; q < 8; ++q) p2[q] = zero2;

        const ull* h1r = (const ull*)&s_h1v[w][e][0];
        const ull* h2r = (const ull*)&s_h2v[w][e][0];
#pragma unroll
        for (int m = 0; m < 8; ++m) {
            const ull hm1 = h1r[m];
            const ull hm2 = h2r[m];
            const ulonglong2 wi0 = s_w2i[m][u][0], wi1 = s_w2i[m][u][1];
            const ulonglong2 wi2 = s_w2i[m][u][2], wi3 = s_w2i[m][u][3];
            const ulonglong2 wh0 = s_w2h[m][u][0], wh1 = s_w2h[m][u][1];
            const ulonglong2 wh2_ = s_w2h[m][u][2], wh3 = s_w2h[m][u][3];
            a2[0] = fma2(wi0.x, hm1, a2[0]); a2[1] = fma2(wi0.y, hm1, a2[1]);
            a2[2] = fma2(wi1.x, hm1, a2[2]); a2[3] = fma2(wi1.y, hm1, a2[3]);
            a2[4] = fma2(wi2.x, hm1, a2[4]); a2[5] = fma2(wi2.y, hm1, a2[5]);
            a2[6] = fma2(wi3.x, hm1, a2[6]); a2[7] = fma2(wi3.y, hm1, a2[7]);
            p2[0] = fma2(wh0.x, hm2, p2[0]); p2[1] = fma2(wh0.y, hm2, p2[1]);
            p2[2] = fma2(wh1.x, hm2, p2[2]); p2[3] = fma2(wh1.y, hm2, p2[3]);
            p2[4] = fma2(wh2_.x, hm2, p2[4]); p2[5] = fma2(wh2_.y, hm2, p2[5]);
            p2[6] = fma2(wh3.x, hm2, p2[6]); p2[7] = fma2(wh3.y, hm2, p2[7]);
#pragma unroll
            for (int q = 0; q < 8; ++q) p1[q] = fma2(w1[q][m], hm1, p1[q]);
        }
#pragma unroll
        for (int q = 0; q < 8; ++q) s2[q] = add2(a2[q], p2[q]);
    };

    auto head = [&](int t) {
        float acc = s_fc1b[u];
        const float* h2f = (const float*)&s_h2v[w][e][0];
#pragma unroll
        for (int k = 0; k < HID; ++k)
            acc = fmaf(s_fc1w[u * HID + k], h2f[k], acc);
        acc = (acc >= 0.f) ? acc : 0.2f * acc;       // LeakyReLU(0.2)
        float p = s_fc2w[u] * acc;
        p += __shfl_xor_sync(0xffffffffu, p, 4);
        p += __shfl_xor_sync(0xffffffffu, p, 2);
        p += __shfl_xor_sync(0xffffffffu, p, 1);
        o_head = p + s_fc2b1[0];                     // all 8 lanes of group agree
        if (u == 0) orow[t - (SEQT - 1)] = o_head;
    };

    // ---- prologue: L1(0); matvec (p2 from zeroed h2 = 0) -> s2(0), p1(1) ----
    l1gates(xrow[0]);
    matvecs();
    float xt1 = xrow[1];

    // ---- teacher steady state: one syncwarp per step ----
#pragma unroll 1
    for (int t = 0; t < SEQT - 1; ++t) {
        l2gates();                  // finish step t     (writes h2(t))
        l1gates(xt1);               // gates of step t+1 (writes h1(t+1))
        xt1 = xrow[(t + 2) & (SEQT - 1)];
        matvecs();                  // p2(t) + a2/p1(t+2); s2(t+1)
    }

    // ---- head + autoregressive phase (33 steps) ----
#pragma unroll 1
    for (int t = SEQT - 1; t < SEQT + FUT; ++t) {
        l2gates();                  // finish step t
        __syncwarp();
        head(t);                    // o_head(t)
        l1gates(o_head);            // gates of step t+1 (input = o_head)
        matvecs();
    }
}

extern "C" void kernel_launch(void* const* d_in, const int* in_sizes, int n_in,
                              void* d_out, int out_size)
{
    const float* x    = (const float*)d_in[0];
    const float* Wih1 = (const float*)d_in[1];
    const float* Whh1 = (const float*)d_in[2];
    const float* bih1 = (const float*)d_in[3];
    const float* bhh1 = (const float*)d_in[4];
    const float* Wih2 = (const float*)d_in[5];
    const float* Whh2 = (const float*)d_in[6];
    const float* bih2 = (const float*)d_in[7];
    const float* bhh2 = (const float*)d_in[8];
    const float* fc1w = (const float*)d_in[9];
    const float* fc1b = (const float*)d_in[10];
    const float* fc2w = (const float*)d_in[11];
    const float* fc2b = (const float*)d_in[12];
    float* out = (float*)d_out;

    // 128 blocks x 128 threads: 1 CTA/SM, exactly ONE warp per SMSP,
    // 4 batch elements per warp (16 per CTA).
    lstm_net_kernel<<<BATCH / (WPB * EPW), 32 * WPB>>>(x, Wih1, Whh1, bih1, bhh1,
                                                       Wih2, Whh2, bih2, bhh2,
                                                       fc1w, fc1b, fc2w, fc2b, out);
}

// round 15
// speedup vs baseline: 10.1529x; 10.1529x over previous
#include <cuda_runtime.h>
#include <cstdint>

#define HID   16
#define BATCH 2048
#define SEQT  2048
#define FUT   32
#define NOUT  (FUT + 1)
#define WPB   8            // 8 warps/CTA, 128 CTAs -> 1 CTA/SM, 2 warps/SMSP uniform

typedef unsigned long long ull;

// ---------- packed f32x2 helpers (sm_103a) ----------
__device__ __forceinline__ ull pack2(float lo, float hi) {
    ull r;
    asm("mov.b64 %0, {%1, %2};" : "=l"(r) : "f"(lo), "f"(hi));
    return r;
}
__device__ __forceinline__ void unpack2(ull v, float& lo, float& hi) {
    asm("mov.b64 {%0, %1}, %2;" : "=f"(lo), "=f"(hi) : "l"(v));
}
__device__ __forceinline__ ull fma2(ull a, ull b, ull c) {
    ull d;
    asm("fma.rn.f32x2 %0, %1, %2, %3;" : "=l"(d) : "l"(a), "l"(b), "l"(c));
    return d;
}
__device__ __forceinline__ ull add2(ull a, ull b) {
    ull d;
    asm("add.rn.f32x2 %0, %1, %2;" : "=l"(d) : "l"(a), "l"(b));
    return d;
}
__device__ __forceinline__ float hadd2(ull v) {
    float lo, hi; unpack2(v, lo, hi); return lo + hi;
}

// ---------- fast activations ----------
__device__ __forceinline__ float tanh_ap(float x) {
    float y;
    asm("tanh.approx.f32 %0, %1;" : "=f"(y) : "f"(x));
    return y;
}
__device__ __forceinline__ float sigm(float x) {
    return fmaf(0.5f, tanh_ap(0.5f * x), 0.5f);
}

// R7 body (best known: 801us), one shared code path, PLUS a one-time ~350-cycle
// phase-offset delay for warps 4..7 (the wid%4 SMSP partners of warps 0..3).
// Co-resident warp pairs then execute the same loop shifted by half a step,
// so MUFU bursts / LDS bursts / serial-chain stalls interleave instead of
// colliding in lockstep. Layer-2 input uses s2 = add2(a2,p2) merge.
__global__ void __launch_bounds__(32 * WPB, 1)
lstm_net_kernel(const float* __restrict__ x,
                const float* __restrict__ Wih1, const float* __restrict__ Whh1,
                const float* __restrict__ bih1, const float* __restrict__ bhh1,
                const float* __restrict__ Wih2, const float* __restrict__ Whh2,
                const float* __restrict__ bih2, const float* __restrict__ bhh2,
                const float* __restrict__ fc1w, const float* __restrict__ fc1b,
                const float* __restrict__ fc2w, const float* __restrict__ fc2b,
                float* __restrict__ out)
{
    __shared__ ulonglong2 s_w2hgo[8][HID];     // Whh2 g/o rows, k-pair packed
    __shared__ float4 s_h1[WPB][2][4];         // h1 broadcast [warp][elem][16f]
    __shared__ float4 s_h2[WPB][2][4];
    __shared__ float s_fc1w[(HID / 2) * HID];
    __shared__ float s_fc1b[HID / 2];
    __shared__ float s_fc2w[HID / 2];
    __shared__ float s_fc2b;
    __shared__ float s_sink;                   // delay-chain sink (never written)

    const int tid = threadIdx.x;
    if (tid < 128) {
        const int m = tid >> 4, jj = tid & 15;
        s_w2hgo[m][jj] = make_ulonglong2(
            pack2(Whh2[(jj + 32) * HID + 2 * m], Whh2[(jj + 32) * HID + 2 * m + 1]),
            pack2(Whh2[(jj + 48) * HID + 2 * m], Whh2[(jj + 48) * HID + 2 * m + 1]));
    }
    if (tid < (HID / 2) * HID) s_fc1w[tid] = fc1w[tid];
    if (tid < HID / 2) { s_fc1b[tid] = fc1b[tid]; s_fc2w[tid] = fc2w[tid]; }
    if (tid == 0) s_fc2b = fc2b[0];
    __syncthreads();

    const int lane = tid & 31;
    const int w    = tid >> 5;
    const int e    = lane >> 4;
    const int j    = lane & 15;
    const int b    = (blockIdx.x * WPB + w) * 2 + e;

    const int r0 = j, r1 = j + HID, r2 = j + 2 * HID, r3 = j + 3 * HID;

    const float wxi = Wih1[r0], wxf = Wih1[r1], wxg = Wih1[r2], wxo = Wih1[r3];
    const ull pb1i = pack2(bih1[r0] + bhh1[r0], 0.f);
    const ull pb1f = pack2(bih1[r1] + bhh1[r1], 0.f);
    const ull pb1g = pack2(bih1[r2] + bhh1[r2], 0.f);
    const ull pb1o = pack2(bih1[r3] + bhh1[r3], 0.f);
    const ull pb2i = pack2(bih2[r0] + bhh2[r0], 0.f);
    const ull pb2f = pack2(bih2[r1] + bhh2[r1], 0.f);
    const ull pb2g = pack2(bih2[r2] + bhh2[r2], 0.f);
    const ull pb2o = pack2(bih2[r3] + bhh2[r3], 0.f);

    // register-resident weights (k-pair packed): 10 arrays x 8 ull = 160 regs
    ull w1i_[8], w1f_[8], w1g_[8], w1o_[8];    // Whh1 (critical path)
    ull w2ii[8], w2if[8], w2ig[8], w2io[8];    // Wih2
    ull w2hi[8], w2hf[8];                      // Whh2 i/f rows
#pragma unroll
    for (int m = 0; m < 8; ++m) {
        w1i_[m] = pack2(Whh1[r0 * HID + 2 * m], Whh1[r0 * HID + 2 * m + 1]);
        w1f_[m] = pack2(Whh1[r1 * HID + 2 * m], Whh1[r1 * HID + 2 * m + 1]);
        w1g_[m] = pack2(Whh1[r2 * HID + 2 * m], Whh1[r2 * HID + 2 * m + 1]);
        w1o_[m] = pack2(Whh1[r3 * HID + 2 * m], Whh1[r3 * HID + 2 * m + 1]);
        w2ii[m] = pack2(Wih2[r0 * HID + 2 * m], Wih2[r0 * HID + 2 * m + 1]);
        w2if[m] = pack2(Wih2[r1 * HID + 2 * m], Wih2[r1 * HID + 2 * m + 1]);
        w2ig[m] = pack2(Wih2[r2 * HID + 2 * m], Wih2[r2 * HID + 2 * m + 1]);
        w2io[m] = pack2(Wih2[r3 * HID + 2 * m], Wih2[r3 * HID + 2 * m + 1]);
        w2hi[m] = pack2(Whh2[r0 * HID + 2 * m], Whh2[r0 * HID + 2 * m + 1]);
        w2hf[m] = pack2(Whh2[r1 * HID + 2 * m], Whh2[r1 * HID + 2 * m + 1]);
    }

    // ---- one-time phase offset for the SMSP-partner warps (w & 4) ----
    if (w & 4) {
        float d = (float)(lane + 1);
#pragma unroll 1
        for (int i = 0; i < 88; ++i)               // 88 dependent FMAs ~ 352 cyc
            d = fmaf(d, 0.9990234f, 1.0f);
        if (d > 1.0e30f) s_sink = d;               // unreachable; keeps the chain
    }

    // carried state. p1* = b1 + Whh1@h1_prev ; p2* = Whh2@h2_prev
    float c1 = 0.f, c2 = 0.f, o_head = 0.f;
    ull p1i = pb1i, p1f = pb1f, p1g = pb1g, p1o = pb1o;
    ull p2i = pack2(0.f, 0.f), p2f = p2i, p2g = p2i, p2o = p2i;

    float* s_h1me = (float*)&s_h1[w][e];
    float* s_h2me = (float*)&s_h2[w][e];
    const ulonglong2* s_h1rd = (const ulonglong2*)&s_h1[w][e];
    const ulonglong2* s_h2rd = (const ulonglong2*)&s_h2[w][e];

    const float* xrow = x + (size_t)b * SEQT;
    float* orow = out + (size_t)b * NOUT;
    float xt = xrow[0];

#pragma unroll 1
    for (int t = 0; t < SEQT + FUT; ++t) {
        const float inp = (t < SEQT) ? xt : o_head;
        xt = xrow[(t + 1) & (SEQT - 1)];

        // ======== layer 1 gates (recurrent part pre-accumulated in p1*) ========
        const float ui = fmaf(wxi, inp, hadd2(p1i));
        const float uf = fmaf(wxf, inp, hadd2(p1f));
        const float ug = fmaf(wxg, inp, hadd2(p1g));
        const float uo = fmaf(wxo, inp, hadd2(p1o));
        const float i1 = sigm(ui), f1 = sigm(uf);
        const float g1 = tanh_ap(ug), o1 = sigm(uo);
        c1 = fmaf(f1, c1, i1 * g1);
        const float h1 = o1 * tanh_ap(c1);

        // ==== broadcast h1; feeds Wih2 (now) + Whh1 (next, in place) ====
        s_h1me[j] = h1;
        __syncwarp();

        ull a2i = pb2i, a2f = pb2f, a2g = pb2g, a2o = pb2o;
        p1i = pb1i; p1f = pb1f; p1g = pb1g; p1o = pb1o;
#pragma unroll
        for (int q = 0; q < 4; ++q) {
            const ulonglong2 hq = s_h1rd[q];          // 2 packed h-pairs
            a2i = fma2(w2ii[2 * q], hq.x, a2i);
            a2f = fma2(w2if[2 * q], hq.x, a2f);
            a2g = fma2(w2ig[2 * q], hq.x, a2g);
            a2o = fma2(w2io[2 * q], hq.x, a2o);
            p1i = fma2(w1i_[2 * q], hq.x, p1i);
            p1f = fma2(w1f_[2 * q], hq.x, p1f);
            p1g = fma2(w1g_[2 * q], hq.x, p1g);
            p1o = fma2(w1o_[2 * q], hq.x, p1o);
            a2i = fma2(w2ii[2 * q + 1], hq.y, a2i);
            a2f = fma2(w2if[2 * q + 1], hq.y, a2f);
            a2g = fma2(w2ig[2 * q + 1], hq.y, a2g);
            a2o = fma2(w2io[2 * q + 1], hq.y, a2o);
            p1i = fma2(w1i_[2 * q + 1], hq.y, p1i);
            p1f = fma2(w1f_[2 * q + 1], hq.y, p1f);
            p1g = fma2(w1g_[2 * q + 1], hq.y, p1g);
            p1o = fma2(w1o_[2 * q + 1], hq.y, p1o);
        }

        // ======== layer 2 gates (merged a2+p2) ========
        const float vi = hadd2(add2(a2i, p2i));
        const float vf = hadd2(add2(a2f, p2f));
        const float vg = hadd2(add2(a2g, p2g));
        const float vo = hadd2(add2(a2o, p2o));
        const float i2 = sigm(vi), f2 = sigm(vf);
        const float g2 = tanh_ap(vg), o2 = sigm(vo);
        c2 = fmaf(f2, c2, i2 * g2);
        const float h2 = o2 * tanh_ap(c2);

        // ==== broadcast h2; pre-accumulate Whh2 @ h2 in place ====
        s_h2me[j] = h2;
        __syncwarp();

        p2i = pack2(0.f, 0.f); p2f = p2i; p2g = p2i; p2o = p2i;
#pragma unroll
        for (int q = 0; q < 4; ++q) {
            const ulonglong2 hq = s_h2rd[q];
            const ulonglong2 wg0 = s_w2hgo[2 * q][j];
            const ulonglong2 wg1 = s_w2hgo[2 * q + 1][j];
            p2i = fma2(w2hi[2 * q], hq.x, p2i);
            p2f = fma2(w2hf[2 * q], hq.x, p2f);
            p2g = fma2(wg0.x, hq.x, p2g);
            p2o = fma2(wg0.y, hq.x, p2o);
            p2i = fma2(w2hi[2 * q + 1], hq.y, p2i);
            p2f = fma2(w2hf[2 * q + 1], hq.y, p2f);
            p2g = fma2(wg1.x, hq.y, p2g);
            p2o = fma2(wg1.y, hq.y, p2o);
        }

        // ======== head (last teacher step + future steps only) ========
        if (t >= SEQT - 1) {
            const int jj = j & 7;
            float acc = s_fc1b[jj];
            const float* h2f = s_h2me;
#pragma unroll
            for (int k = 0; k < HID; ++k)
                acc = fmaf(s_fc1w[jj * HID + k], h2f[k], acc);
            acc = (acc >= 0.f) ? acc : 0.2f * acc;      // LeakyReLU(0.2)
            float p = (j < 8) ? s_fc2w[jj] * acc : 0.f;
            p += __shfl_xor_sync(0xffffffffu, p, 8);
            p += __shfl_xor_sync(0xffffffffu, p, 4);
            p += __shfl_xor_sync(0xffffffffu, p, 2);
            p += __shfl_xor_sync(0xffffffffu, p, 1);
            o_head = p + s_fc2b;
            if (j == 0) orow[t - (SEQT - 1)] = o_head;
        }
    }
}

extern "C" void kernel_launch(void* const* d_in, const int* in_sizes, int n_in,
                              void* d_out, int out_size)
{
    const float* x    = (const float*)d_in[0];
    const float* Wih1 = (const float*)d_in[1];
    const float* Whh1 = (const float*)d_in[2];
    const float* bih1 = (const float*)d_in[3];
    const float* bhh1 = (const float*)d_in[4];
    const float* Wih2 = (const float*)d_in[5];
    const float* Whh2 = (const float*)d_in[6];
    const float* bih2 = (const float*)d_in[7];
    const float* bhh2 = (const float*)d_in[8];
    const float* fc1w = (const float*)d_in[9];
    const float* fc1b = (const float*)d_in[10];
    const float* fc2w = (const float*)d_in[11];
    const float* fc2b = (const float*)d_in[12];
    float* out = (float*)d_out;

    // 128 blocks x 256 threads: 1 CTA/SM, exactly 2 warps/SMSP everywhere;
    // partner warps (w & 4) start ~350 cycles phase-shifted.
    lstm_net_kernel<<<BATCH / 16, 32 * WPB>>>(x, Wih1, Whh1, bih1, bhh1,
                                              Wih2, Whh2, bih2, bhh2,
                                              fc1w, fc1b, fc2w, fc2b, out);
}

// round 16
// speedup vs baseline: 10.5312x; 1.0373x over previous
#include <cuda_runtime.h>
#include <cstdint>

#define HID   16
#define BATCH 2048
#define SEQT  2048
#define FUT   32
#define NOUT  (FUT + 1)
#define WPB   8            // 8 warps/CTA, 128 CTAs -> 1 CTA/SM, 2 warps/SMSP uniform

typedef unsigned long long ull;

// ---------- packed f32x2 helpers (sm_103a) ----------
__device__ __forceinline__ ull pack2(float lo, float hi) {
    ull r;
    asm("mov.b64 %0, {%1, %2};" : "=l"(r) : "f"(lo), "f"(hi));
    return r;
}
__device__ __forceinline__ void unpack2(ull v, float& lo, float& hi) {
    asm("mov.b64 {%0, %1}, %2;" : "=f"(lo), "=f"(hi) : "l"(v));
}
__device__ __forceinline__ ull fma2(ull a, ull b, ull c) {
    ull d;
    asm("fma.rn.f32x2 %0, %1, %2, %3;" : "=l"(d) : "l"(a), "l"(b), "l"(c));
    return d;
}
__device__ __forceinline__ ull add2(ull a, ull b) {
    ull d;
    asm("add.rn.f32x2 %0, %1, %2;" : "=l"(d) : "l"(a), "l"(b));
    return d;
}
__device__ __forceinline__ float hadd2(ull v) {
    float lo, hi; unpack2(v, lo, hi); return lo + hi;
}

// ---------- fast activations ----------
__device__ __forceinline__ float tanh_ap(float x) {
    float y;
    asm("tanh.approx.f32 %0, %1;" : "=f"(y) : "f"(x));
    return y;
}
// sigmoid with PRE-HALVED preactivation u = x/2 (weights folded):
__device__ __forceinline__ float sigm_h(float u) {
    return fmaf(0.5f, tanh_ap(u), 0.5f);
}

// R14 winner (768us) + (1) 0.5 pre-scaled i/f/o rows (sigm loses its FMUL),
// (2) split hot teacher loop vs tail loop (no SEL/mask/head-branch in hot path),
// (3) phase-stagger for SMSP partner warps retained.
// Row scale: s(r) = 0.5 for gate rows i (0..15), f (16..31), o (48..63); 1 for g.
__global__ void __launch_bounds__(32 * WPB, 1)
lstm_net_kernel(const float* __restrict__ x,
                const float* __restrict__ Wih1, const float* __restrict__ Whh1,
                const float* __restrict__ bih1, const float* __restrict__ bhh1,
                const float* __restrict__ Wih2, const float* __restrict__ Whh2,
                const float* __restrict__ bih2, const float* __restrict__ bhh2,
                const float* __restrict__ fc1w, const float* __restrict__ fc1b,
                const float* __restrict__ fc2w, const float* __restrict__ fc2b,
                float* __restrict__ out)
{
    __shared__ ulonglong2 s_w2hgo[8][HID];     // Whh2 g/o rows, k-pair packed (o pre-scaled)
    __shared__ float4 s_h1[WPB][2][4];         // h1 broadcast [warp][elem][16f]
    __shared__ float4 s_h2[WPB][2][4];
    __shared__ float s_fc1w[(HID / 2) * HID];
    __shared__ float s_fc1b[HID / 2];
    __shared__ float s_fc2w[HID / 2];
    __shared__ float s_fc2b;
    __shared__ float s_sink;

    const int tid = threadIdx.x;
    if (tid < 128) {
        const int m = tid >> 4, jj = tid & 15;
        // g rows unscaled, o rows scaled 0.5
        s_w2hgo[m][jj] = make_ulonglong2(
            pack2(Whh2[(jj + 32) * HID + 2 * m], Whh2[(jj + 32) * HID + 2 * m + 1]),
            pack2(0.5f * Whh2[(jj + 48) * HID + 2 * m],
                  0.5f * Whh2[(jj + 48) * HID + 2 * m + 1]));
    }
    if (tid < (HID / 2) * HID) s_fc1w[tid] = fc1w[tid];
    if (tid < HID / 2) { s_fc1b[tid] = fc1b[tid]; s_fc2w[tid] = fc2w[tid]; }
    if (tid == 0) s_fc2b = fc2b[0];
    __syncthreads();

    const int lane = tid & 31;
    const int w    = tid >> 5;
    const int e    = lane >> 4;
    const int j    = lane & 15;
    const int b    = (blockIdx.x * WPB + w) * 2 + e;

    const int r0 = j, r1 = j + HID, r2 = j + 2 * HID, r3 = j + 3 * HID;

    // pre-scaled input weights + fused biases (i,f,o rows x0.5; g row x1)
    const float wxi = 0.5f * Wih1[r0], wxf = 0.5f * Wih1[r1];
    const float wxg = Wih1[r2],        wxo = 0.5f * Wih1[r3];
    const ull pb1i = pack2(0.5f * (bih1[r0] + bhh1[r0]), 0.f);
    const ull pb1f = pack2(0.5f * (bih1[r1] + bhh1[r1]), 0.f);
    const ull pb1g = pack2(bih1[r2] + bhh1[r2], 0.f);
    const ull pb1o = pack2(0.5f * (bih1[r3] + bhh1[r3]), 0.f);
    const ull pb2i = pack2(0.5f * (bih2[r0] + bhh2[r0]), 0.f);
    const ull pb2f = pack2(0.5f * (bih2[r1] + bhh2[r1]), 0.f);
    const ull pb2g = pack2(bih2[r2] + bhh2[r2], 0.f);
    const ull pb2o = pack2(0.5f * (bih2[r3] + bhh2[r3]), 0.f);

    // register-resident weights (k-pair packed, i/f/o rows pre-scaled)
    ull w1i_[8], w1f_[8], w1g_[8], w1o_[8];    // Whh1 (critical path)
    ull w2ii[8], w2if[8], w2ig[8], w2io[8];    // Wih2
    ull w2hi[8], w2hf[8];                      // Whh2 i/f rows
#pragma unroll
    for (int m = 0; m < 8; ++m) {
        w1i_[m] = pack2(0.5f * Whh1[r0 * HID + 2 * m], 0.5f * Whh1[r0 * HID + 2 * m + 1]);
        w1f_[m] = pack2(0.5f * Whh1[r1 * HID + 2 * m], 0.5f * Whh1[r1 * HID + 2 * m + 1]);
        w1g_[m] = pack2(Whh1[r2 * HID + 2 * m],        Whh1[r2 * HID + 2 * m + 1]);
        w1o_[m] = pack2(0.5f * Whh1[r3 * HID + 2 * m], 0.5f * Whh1[r3 * HID + 2 * m + 1]);
        w2ii[m] = pack2(0.5f * Wih2[r0 * HID + 2 * m], 0.5f * Wih2[r0 * HID + 2 * m + 1]);
        w2if[m] = pack2(0.5f * Wih2[r1 * HID + 2 * m], 0.5f * Wih2[r1 * HID + 2 * m + 1]);
        w2ig[m] = pack2(Wih2[r2 * HID + 2 * m],        Wih2[r2 * HID + 2 * m + 1]);
        w2io[m] = pack2(0.5f * Wih2[r3 * HID + 2 * m], 0.5f * Wih2[r3 * HID + 2 * m + 1]);
        w2hi[m] = pack2(0.5f * Whh2[r0 * HID + 2 * m], 0.5f * Whh2[r0 * HID + 2 * m + 1]);
        w2hf[m] = pack2(0.5f * Whh2[r1 * HID + 2 * m], 0.5f * Whh2[r1 * HID + 2 * m + 1]);
    }

    // ---- one-time phase offset for the SMSP-partner warps (w & 4) ----
    if (w & 4) {
        float d = (float)(lane + 1);
#pragma unroll 1
        for (int i = 0; i < 88; ++i)
            d = fmaf(d, 0.9990234f, 1.0f);
        if (d > 1.0e30f) s_sink = d;
    }

    // carried state
    float c1 = 0.f, c2 = 0.f, o_head = 0.f;
    ull p1i = pb1i, p1f = pb1f, p1g = pb1g, p1o = pb1o;
    ull p2i = pack2(0.f, 0.f), p2f = p2i, p2g = p2i, p2o = p2i;

    float* s_h1me = (float*)&s_h1[w][e];
    float* s_h2me = (float*)&s_h2[w][e];
    const ulonglong2* s_h1rd = (const ulonglong2*)&s_h1[w][e];
    const ulonglong2* s_h2rd = (const ulonglong2*)&s_h2[w][e];

    const float* xrow = x + (size_t)b * SEQT;
    float* orow = out + (size_t)b * NOUT;
    float xt = xrow[0];

    // ---- shared step body (input given; returns nothing, updates state) ----
    auto step_body = [&](float inp) {
        // layer 1 gates (i/f/o preacts arrive pre-halved)
        const float ui = fmaf(wxi, inp, hadd2(p1i));
        const float uf = fmaf(wxf, inp, hadd2(p1f));
        const float ug = fmaf(wxg, inp, hadd2(p1g));
        const float uo = fmaf(wxo, inp, hadd2(p1o));
        const float i1 = sigm_h(ui), f1 = sigm_h(uf);
        const float g1 = tanh_ap(ug), o1 = sigm_h(uo);
        c1 = fmaf(f1, c1, i1 * g1);
        const float h1 = o1 * tanh_ap(c1);

        s_h1me[j] = h1;
        __syncwarp();

        ull a2i = pb2i, a2f = pb2f, a2g = pb2g, a2o = pb2o;
        p1i = pb1i; p1f = pb1f; p1g = pb1g; p1o = pb1o;
#pragma unroll
        for (int q = 0; q < 4; ++q) {
            const ulonglong2 hq = s_h1rd[q];
            a2i = fma2(w2ii[2 * q], hq.x, a2i);
            a2f = fma2(w2if[2 * q], hq.x, a2f);
            a2g = fma2(w2ig[2 * q], hq.x, a2g);
            a2o = fma2(w2io[2 * q], hq.x, a2o);
            p1i = fma2(w1i_[2 * q], hq.x, p1i);
            p1f = fma2(w1f_[2 * q], hq.x, p1f);
            p1g = fma2(w1g_[2 * q], hq.x, p1g);
            p1o = fma2(w1o_[2 * q], hq.x, p1o);
            a2i = fma2(w2ii[2 * q + 1], hq.y, a2i);
            a2f = fma2(w2if[2 * q + 1], hq.y, a2f);
            a2g = fma2(w2ig[2 * q + 1], hq.y, a2g);
            a2o = fma2(w2io[2 * q + 1], hq.y, a2o);
            p1i = fma2(w1i_[2 * q + 1], hq.y, p1i);
            p1f = fma2(w1f_[2 * q + 1], hq.y, p1f);
            p1g = fma2(w1g_[2 * q + 1], hq.y, p1g);
            p1o = fma2(w1o_[2 * q + 1], hq.y, p1o);
        }

        // layer 2 gates
        const float vi = hadd2(add2(a2i, p2i));
        const float vf = hadd2(add2(a2f, p2f));
        const float vg = hadd2(add2(a2g, p2g));
        const float vo = hadd2(add2(a2o, p2o));
        const float i2 = sigm_h(vi), f2 = sigm_h(vf);
        const float g2 = tanh_ap(vg), o2 = sigm_h(vo);
        c2 = fmaf(f2, c2, i2 * g2);
        const float h2 = o2 * tanh_ap(c2);

        s_h2me[j] = h2;
        __syncwarp();

        p2i = pack2(0.f, 0.f); p2f = p2i; p2g = p2i; p2o = p2i;
#pragma unroll
        for (int q = 0; q < 4; ++q) {
            const ulonglong2 hq = s_h2rd[q];
            const ulonglong2 wg0 = s_w2hgo[2 * q][j];
            const ulonglong2 wg1 = s_w2hgo[2 * q + 1][j];
            p2i = fma2(w2hi[2 * q], hq.x, p2i);
            p2f = fma2(w2hf[2 * q], hq.x, p2f);
            p2g = fma2(wg0.x, hq.x, p2g);
            p2o = fma2(wg0.y, hq.x, p2o);
            p2i = fma2(w2hi[2 * q + 1], hq.y, p2i);
            p2f = fma2(w2hf[2 * q + 1], hq.y, p2f);
            p2g = fma2(wg1.x, hq.y, p2g);
            p2o = fma2(wg1.y, hq.y, p2o);
        }
    };

    // ---- hot teacher loop: no SEL, no masking, no head branch ----
#pragma unroll 1
    for (int t = 0; t < SEQT - 1; ++t) {
        const float inp = xt;
        xt = xrow[t + 1];          // t+1 <= SEQT-1: always in bounds
        step_body(inp);
    }

    // ---- tail: last teacher step + 32 autoregressive steps, with head ----
#pragma unroll 1
    for (int t = SEQT - 1; t < SEQT + FUT; ++t) {
        const float inp = (t == SEQT - 1) ? xt : o_head;
        step_body(inp);

        const int jj = j & 7;
        float acc = s_fc1b[jj];
#pragma unroll
        for (int k = 0; k < HID; ++k)
            acc = fmaf(s_fc1w[jj * HID + k], s_h2me[k], acc);
        acc = (acc >= 0.f) ? acc : 0.2f * acc;          // LeakyReLU(0.2)
        float p = (j < 8) ? s_fc2w[jj] * acc : 0.f;
        p += __shfl_xor_sync(0xffffffffu, p, 8);
        p += __shfl_xor_sync(0xffffffffu, p, 4);
        p += __shfl_xor_sync(0xffffffffu, p, 2);
        p += __shfl_xor_sync(0xffffffffu, p, 1);
        o_head = p + s_fc2b;
        if (j == 0) orow[t - (SEQT - 1)] = o_head;
    }
}

extern "C" void kernel_launch(void* const* d_in, const int* in_sizes, int n_in,
                              void* d_out, int out_size)
{
    const float* x    = (const float*)d_in[0];
    const float* Wih1 = (const float*)d_in[1];
    const float* Whh1 = (const float*)d_in[2];
    const float* bih1 = (const float*)d_in[3];
    const float* bhh1 = (const float*)d_in[4];
    const float* Wih2 = (const float*)d_in[5];
    const float* Whh2 = (const float*)d_in[6];
    const float* bih2 = (const float*)d_in[7];
    const float* bhh2 = (const float*)d_in[8];
    const float* fc1w = (const float*)d_in[9];
    const float* fc1b = (const float*)d_in[10];
    const float* fc2w = (const float*)d_in[11];
    const float* fc2b = (const float*)d_in[12];
    float* out = (float*)d_out;

    // 128 blocks x 256 threads: 1 CTA/SM, 2 warps/SMSP, phase-staggered pairs
    lstm_net_kernel<<<BATCH / 16, 32 * WPB>>>(x, Wih1, Whh1, bih1, bhh1,
                                              Wih2, Whh2, bih2, bhh2,
                                              fc1w, fc1b, fc2w, fc2b, out);
}

// round 17
// speedup vs baseline: 11.1976x; 1.0633x over previous
#include <cuda_runtime.h>
#include <cstdint>

#define HID   16
#define BATCH 2048
#define SEQT  2048
#define FUT   32
#define NOUT  (FUT + 1)
#define WPB   8            // 8 warps/CTA, 128 CTAs -> 1 CTA/SM, 2 warps/SMSP uniform

typedef unsigned long long ull;

// ---------- packed f32x2 helpers (sm_103a) ----------
__device__ __forceinline__ ull pack2(float lo, float hi) {
    ull r;
    asm("mov.b64 %0, {%1, %2};" : "=l"(r) : "f"(lo), "f"(hi));
    return r;
}
__device__ __forceinline__ void unpack2(ull v, float& lo, float& hi) {
    asm("mov.b64 {%0, %1}, %2;" : "=f"(lo), "=f"(hi) : "l"(v));
}
__device__ __forceinline__ ull fma2(ull a, ull b, ull c) {
    ull d;
    asm("fma.rn.f32x2 %0, %1, %2, %3;" : "=l"(d) : "l"(a), "l"(b), "l"(c));
    return d;
}
__device__ __forceinline__ ull add2(ull a, ull b) {
    ull d;
    asm("add.rn.f32x2 %0, %1, %2;" : "=l"(d) : "l"(a), "l"(b));
    return d;
}
__device__ __forceinline__ float hadd2(ull v) {
    float lo, hi; unpack2(v, lo, hi); return lo + hi;
}

// ---------- fast activations ----------
__device__ __forceinline__ float tanh_ap(float x) {
    float y;
    asm("tanh.approx.f32 %0, %1;" : "=f"(y) : "f"(x));
    return y;
}
// sigmoid with PRE-HALVED preactivation u = x/2 (weights folded):
__device__ __forceinline__ float sigm_h(float u) {
    return fmaf(0.5f, tanh_ap(u), 0.5f);
}

// 741us winner + SINGLE-SYNC RESTRUCTURE: per hot step,
//   [L2-gates(t) ; L1-gates(t+1)]  (independent; MUFUs pipeline together)
//   -> STS h2(t), STS h1(t+1) -> ONE syncwarp ->
//   [matvec A: a2(t+1), p1(t+2) from h1]  [matvec B: p2(t+1) from h2]
//   -> s2(t+1) = add2(a2, p2)
// Tail loop (last teacher + 32 AR steps) uses the 2-sync path with the head.
// Keeps: phase-stagger (w&4), 0.5-prescaled i/f/o rows, reg/smem weight split.
__global__ void __launch_bounds__(32 * WPB, 1)
lstm_net_kernel(const float* __restrict__ x,
                const float* __restrict__ Wih1, const float* __restrict__ Whh1,
                const float* __restrict__ bih1, const float* __restrict__ bhh1,
                const float* __restrict__ Wih2, const float* __restrict__ Whh2,
                const float* __restrict__ bih2, const float* __restrict__ bhh2,
                const float* __restrict__ fc1w, const float* __restrict__ fc1b,
                const float* __restrict__ fc2w, const float* __restrict__ fc2b,
                float* __restrict__ out)
{
    __shared__ ulonglong2 s_w2hgo[8][HID];     // Whh2 g/o rows (o pre-scaled)
    __shared__ float4 s_h1[WPB][2][4];         // h1 broadcast [warp][elem][16f]
    __shared__ float4 s_h2[WPB][2][4];
    __shared__ float s_fc1w[(HID / 2) * HID];
    __shared__ float s_fc1b[HID / 2];
    __shared__ float s_fc2w[HID / 2];
    __shared__ float s_fc2b;
    __shared__ float s_sink;

    const int tid = threadIdx.x;
    if (tid < 128) {
        const int m = tid >> 4, jj = tid & 15;
        s_w2hgo[m][jj] = make_ulonglong2(
            pack2(Whh2[(jj + 32) * HID + 2 * m], Whh2[(jj + 32) * HID + 2 * m + 1]),
            pack2(0.5f * Whh2[(jj + 48) * HID + 2 * m],
                  0.5f * Whh2[(jj + 48) * HID + 2 * m + 1]));
    }
    if (tid < (HID / 2) * HID) s_fc1w[tid] = fc1w[tid];
    if (tid < HID / 2) { s_fc1b[tid] = fc1b[tid]; s_fc2w[tid] = fc2w[tid]; }
    if (tid == 0) s_fc2b = fc2b[0];
    __syncthreads();

    const int lane = tid & 31;
    const int w    = tid >> 5;
    const int e    = lane >> 4;
    const int j    = lane & 15;
    const int b    = (blockIdx.x * WPB + w) * 2 + e;

    const int r0 = j, r1 = j + HID, r2 = j + 2 * HID, r3 = j + 3 * HID;

    // pre-scaled input weights + fused biases (i,f,o rows x0.5; g row x1)
    const float wxi = 0.5f * Wih1[r0], wxf = 0.5f * Wih1[r1];
    const float wxg = Wih1[r2],        wxo = 0.5f * Wih1[r3];
    const ull pb1i = pack2(0.5f * (bih1[r0] + bhh1[r0]), 0.f);
    const ull pb1f = pack2(0.5f * (bih1[r1] + bhh1[r1]), 0.f);
    const ull pb1g = pack2(bih1[r2] + bhh1[r2], 0.f);
    const ull pb1o = pack2(0.5f * (bih1[r3] + bhh1[r3]), 0.f);
    const ull pb2i = pack2(0.5f * (bih2[r0] + bhh2[r0]), 0.f);
    const ull pb2f = pack2(0.5f * (bih2[r1] + bhh2[r1]), 0.f);
    const ull pb2g = pack2(bih2[r2] + bhh2[r2], 0.f);
    const ull pb2o = pack2(0.5f * (bih2[r3] + bhh2[r3]), 0.f);

    // register-resident weights (k-pair packed, i/f/o rows pre-scaled)
    ull w1i_[8], w1f_[8], w1g_[8], w1o_[8];    // Whh1
    ull w2ii[8], w2if[8], w2ig[8], w2io[8];    // Wih2
    ull w2hi[8], w2hf[8];                      // Whh2 i/f rows
#pragma unroll
    for (int m = 0; m < 8; ++m) {
        w1i_[m] = pack2(0.5f * Whh1[r0 * HID + 2 * m], 0.5f * Whh1[r0 * HID + 2 * m + 1]);
        w1f_[m] = pack2(0.5f * Whh1[r1 * HID + 2 * m], 0.5f * Whh1[r1 * HID + 2 * m + 1]);
        w1g_[m] = pack2(Whh1[r2 * HID + 2 * m],        Whh1[r2 * HID + 2 * m + 1]);
        w1o_[m] = pack2(0.5f * Whh1[r3 * HID + 2 * m], 0.5f * Whh1[r3 * HID + 2 * m + 1]);
        w2ii[m] = pack2(0.5f * Wih2[r0 * HID + 2 * m], 0.5f * Wih2[r0 * HID + 2 * m + 1]);
        w2if[m] = pack2(0.5f * Wih2[r1 * HID + 2 * m], 0.5f * Wih2[r1 * HID + 2 * m + 1]);
        w2ig[m] = pack2(Wih2[r2 * HID + 2 * m],        Wih2[r2 * HID + 2 * m + 1]);
        w2io[m] = pack2(0.5f * Wih2[r3 * HID + 2 * m], 0.5f * Wih2[r3 * HID + 2 * m + 1]);
        w2hi[m] = pack2(0.5f * Whh2[r0 * HID + 2 * m], 0.5f * Whh2[r0 * HID + 2 * m + 1]);
        w2hf[m] = pack2(0.5f * Whh2[r1 * HID + 2 * m], 0.5f * Whh2[r1 * HID + 2 * m + 1]);
    }

    // ---- one-time phase offset for the SMSP-partner warps (w & 4) ----
    if (w & 4) {
        float d = (float)(lane + 1);
#pragma unroll 1
        for (int i = 0; i < 88; ++i)
            d = fmaf(d, 0.9990234f, 1.0f);
        if (d > 1.0e30f) s_sink = d;
    }

    // carried state
    float c1 = 0.f, c2 = 0.f, o_head = 0.f;
    ull p1i = pb1i, p1f = pb1f, p1g = pb1g, p1o = pb1o;  // b1 + Whh1@h1_prev
    ull s2i, s2f, s2g, s2o;                               // layer-2 input sums
    ull p2i = pack2(0.f, 0.f), p2f = p2i, p2g = p2i, p2o = p2i;

    float* s_h1me = (float*)&s_h1[w][e];
    float* s_h2me = (float*)&s_h2[w][e];
    const ulonglong2* s_h1rd = (const ulonglong2*)&s_h1[w][e];
    const ulonglong2* s_h2rd = (const ulonglong2*)&s_h2[w][e];

    const float* xrow = x + (size_t)b * SEQT;
    float* orow = out + (size_t)b * NOUT;

    // ---- segment lambdas ----
    auto l1gates = [&](float inp) {                 // p1 -> h1 (stored, not synced)
        const float ui = fmaf(wxi, inp, hadd2(p1i));
        const float uf = fmaf(wxf, inp, hadd2(p1f));
        const float ug = fmaf(wxg, inp, hadd2(p1g));
        const float uo = fmaf(wxo, inp, hadd2(p1o));
        const float i1 = sigm_h(ui), f1 = sigm_h(uf);
        const float g1 = tanh_ap(ug), o1 = sigm_h(uo);
        c1 = fmaf(f1, c1, i1 * g1);
        s_h1me[j] = o1 * tanh_ap(c1);
    };

    auto l2gates = [&]() {                          // s2 -> h2 (stored, not synced)
        const float vi = hadd2(s2i), vf = hadd2(s2f);
        const float vg = hadd2(s2g), vo = hadd2(s2o);
        const float i2 = sigm_h(vi), f2 = sigm_h(vf);
        const float g2 = tanh_ap(vg), o2 = sigm_h(vo);
        c2 = fmaf(f2, c2, i2 * g2);
        s_h2me[j] = o2 * tanh_ap(c2);
    };

    // matvec A: a2 = b2 + Wih2@h1 ; p1 = b1 + Whh1@h1 (in place). Leaves a2 in s2.
    auto matvecA = [&]() {
        ull a2i = pb2i, a2f = pb2f, a2g = pb2g, a2o = pb2o;
        p1i = pb1i; p1f = pb1f; p1g = pb1g; p1o = pb1o;
#pragma unroll
        for (int q = 0; q < 4; ++q) {
            const ulonglong2 hq = s_h1rd[q];
            a2i = fma2(w2ii[2 * q], hq.x, a2i);
            a2f = fma2(w2if[2 * q], hq.x, a2f);
            a2g = fma2(w2ig[2 * q], hq.x, a2g);
            a2o = fma2(w2io[2 * q], hq.x, a2o);
            p1i = fma2(w1i_[2 * q], hq.x, p1i);
            p1f = fma2(w1f_[2 * q], hq.x, p1f);
            p1g = fma2(w1g_[2 * q], hq.x, p1g);
            p1o = fma2(w1o_[2 * q], hq.x, p1o);
            a2i = fma2(w2ii[2 * q + 1], hq.y, a2i);
            a2f = fma2(w2if[2 * q + 1], hq.y, a2f);
            a2g = fma2(w2ig[2 * q + 1], hq.y, a2g);
            a2o = fma2(w2io[2 * q + 1], hq.y, a2o);
            p1i = fma2(w1i_[2 * q + 1], hq.y, p1i);
            p1f = fma2(w1f_[2 * q + 1], hq.y, p1f);
            p1g = fma2(w1g_[2 * q + 1], hq.y, p1g);
            p1o = fma2(w1o_[2 * q + 1], hq.y, p1o);
        }
        s2i = a2i; s2f = a2f; s2g = a2g; s2o = a2o;
    };

    // matvec B: p2 = Whh2@h2 ; then fold into s2.
    auto matvecB = [&]() {
        p2i = pack2(0.f, 0.f); p2f = p2i; p2g = p2i; p2o = p2i;
#pragma unroll
        for (int q = 0; q < 4; ++q) {
            const ulonglong2 hq = s_h2rd[q];
            const ulonglong2 wg0 = s_w2hgo[2 * q][j];
            const ulonglong2 wg1 = s_w2hgo[2 * q + 1][j];
            p2i = fma2(w2hi[2 * q], hq.x, p2i);
            p2f = fma2(w2hf[2 * q], hq.x, p2f);
            p2g = fma2(wg0.x, hq.x, p2g);
            p2o = fma2(wg0.y, hq.x, p2o);
            p2i = fma2(w2hi[2 * q + 1], hq.y, p2i);
            p2f = fma2(w2hf[2 * q + 1], hq.y, p2f);
            p2g = fma2(wg1.x, hq.y, p2g);
            p2o = fma2(wg1.y, hq.y, p2o);
        }
        s2i = add2(s2i, p2i); s2f = add2(s2f, p2f);
        s2g = add2(s2g, p2g); s2o = add2(s2o, p2o);
    };

    // ---- prologue: L1(0); sync; matvec A -> s2(0) (p2(−1)=0), p1(1) ----
    l1gates(xrow[0]);
    __syncwarp();
    matvecA();                     // s2(0) = a2(0); p2 currently 0 -> fold
    s2i = add2(s2i, p2i); s2f = add2(s2f, p2f);
    s2g = add2(s2g, p2g); s2o = add2(s2o, p2o);
    float xt = xrow[1];

    // ---- hot teacher loop: ONE syncwarp per step ----
#pragma unroll 1
    for (int t = 0; t < SEQT - 1; ++t) {
        l2gates();                 // h2(t) from s2(t)      [STS]
        l1gates(xt);               // h1(t+1) from p1(t+1)  [STS]
        xt = xrow[(t + 2) & (SEQT - 1)];
        __syncwarp();
        matvecA();                 // a2(t+1), p1(t+2) from h1(t+1)
        matvecB();                 // p2(t+1) from h2(t); s2(t+1) folded
    }

    // ---- tail: last teacher step + 32 autoregressive steps, with head ----
#pragma unroll 1
    for (int t = SEQT - 1; t < SEQT + FUT; ++t) {
        l2gates();                 // h2(t)
        __syncwarp();

        const int jj = j & 7;
        float acc = s_fc1b[jj];
#pragma unroll
        for (int k = 0; k < HID; ++k)
            acc = fmaf(s_fc1w[jj * HID + k], s_h2me[k], acc);
        acc = (acc >= 0.f) ? acc : 0.2f * acc;          // LeakyReLU(0.2)
        float p = (j < 8) ? s_fc2w[jj] * acc : 0.f;
        p += __shfl_xor_sync(0xffffffffu, p, 8);
        p += __shfl_xor_sync(0xffffffffu, p, 4);
        p += __shfl_xor_sync(0xffffffffu, p, 2);
        p += __shfl_xor_sync(0xffffffffu, p, 1);
        o_head = p + s_fc2b;
        if (j == 0) orow[t - (SEQT - 1)] = o_head;

        l1gates(o_head);           // h1(t+1), input = o_head
        __syncwarp();
        matvecA();
        matvecB();
    }
}

extern "C" void kernel_launch(void* const* d_in, const int* in_sizes, int n_in,
                              void* d_out, int out_size)
{
    const float* x    = (const float*)d_in[0];
    const float* Wih1 = (const float*)d_in[1];
    const float* Whh1 = (const float*)d_in[2];
    const float* bih1 = (const float*)d_in[3];
    const float* bhh1 = (const float*)d_in[4];
    const float* Wih2 = (const float*)d_in[5];
    const float* Whh2 = (const float*)d_in[6];
    const float* bih2 = (const float*)d_in[7];
    const float* bhh2 = (const float*)d_in[8];
    const float* fc1w = (const float*)d_in[9];
    const float* fc1b = (const float*)d_in[10];
    const float* fc2w = (const float*)d_in[11];
    const float* fc2b = (const float*)d_in[12];
    float* out = (float*)d_out;

    // 128 blocks x 256 threads: 1 CTA/SM, 2 warps/SMSP, phase-staggered pairs
    lstm_net_kernel<<<BATCH / 16, 32 * WPB>>>(x, Wih1, Whh1, bih1, bhh1,
                                              Wih2, Whh2, bih2, bhh2,
                                              fc1w, fc1b, fc2w, fc2b, out);
}